// round 14
// baseline (speedup 1.0000x reference)
#include <cuda_runtime.h>

#define Bc 4
#define Nc 8192
#define NPc 2048
#define NSc 32
#define CINc 128
#define COUTc 256

// Scratch (no cudaMalloc allowed): device globals
__device__ int   g_fidx[Bc * NPc];
__device__ float g_featsT[(size_t)Bc * Nc * CINc];    // [B, N, CIN]  16 MB
__device__ float g_pooledT[(size_t)Bc * NPc * CINc];  // [B, NP, CIN]  4 MB

// ---------------- packed f32x2 helpers (sm_103a) ----------------
// NOTE: only add/mul/fma exist in f32x2 form; min/max do NOT (ptxas rejects).
typedef unsigned long long ull;

__device__ __forceinline__ ull f2pack(float lo, float hi) {
    ull r; asm("mov.b64 %0, {%1, %2};" : "=l"(r) : "f"(lo), "f"(hi)); return r;
}
__device__ __forceinline__ float2 f2unpack(ull v) {
    float2 f; asm("mov.b64 {%0, %1}, %2;" : "=f"(f.x), "=f"(f.y) : "l"(v)); return f;
}
__device__ __forceinline__ ull f2add(ull a, ull b) {
    ull r; asm("add.rn.f32x2 %0, %1, %2;" : "=l"(r) : "l"(a), "l"(b)); return r;
}
__device__ __forceinline__ ull f2mul(ull a, ull b) {
    ull r; asm("mul.rn.f32x2 %0, %1, %2;" : "=l"(r) : "l"(a), "l"(b)); return r;
}
__device__ __forceinline__ ull f2fma(ull a, ull b, ull c) {
    ull r; asm("fma.rn.f32x2 %0, %1, %2, %3;" : "=l"(r) : "l"(a), "l"(b), "l"(c)); return r;
}

__device__ __forceinline__ unsigned expand6(unsigned v) {  // 6 bits -> every 3rd bit
    v = (v * 0x00010001u) & 0xFF0000FFu;
    v = (v * 0x00000101u) & 0x0F00F00Fu;
    v = (v * 0x00000011u) & 0xC30C30C3u;
    v = (v * 0x00000005u) & 0x49249249u;
    return v;
}

// ---------------------------------------------------------------------------
// 1) Furthest point sampling (512 threads/block, 16 Morton-contiguous points
//    per thread, bitonic-sorted in shared, exact per-thread bounding-sphere
//    pruning; flat, branch-minimal).
//    Stage 1 now has NO collective: every lane atomicMax's an ordering-exact
//    u64 key  (value_bits << 32) | (8191 - candc)  into its warp's own slot
//    (lane 0 ST.64-resets the slot first; same-warp same-address shared ops
//    complete in program order -> write-before-use, no extra buffering).
//    u64 max == (max value, min original index): distances >= 0 so unsigned
//    order == float order; low 13 bits inverted index. candc always valid:
//    bv = fmax tree over mind returns one of its args bit-exactly.
//    Stage 2 (after ONE __syncthreads): one LDS.64 per lane (16 slots),
//    REDUX.MAX on value + REDUX.MIN on matching index.
//    Double-buffered by parity. candc + squared prune threshold cached,
//    recomputed only in the update branch. Tie-break = lowest original index.
// ---------------------------------------------------------------------------
__global__ void __launch_bounds__(512, 1) fps_kernel(const float* __restrict__ xyz) {
    const int b = blockIdx.x;
    const float* xb = xyz + (size_t)b * Nc * 3;
    const int t = threadIdx.x;
    const int lane = t & 31;
    const int wid = t >> 5;

    __shared__ unsigned skey[Nc];               // 32 KB: (morton18 << 13) | idx13
    __shared__ __align__(16) ull skeys[2][16];  // per-warp packed u64 keys

    // ---- phase A: build sort keys ----
#pragma unroll
    for (int r = 0; r < 16; r++) {
        const int i = t + r * 512;
        const float x = xb[3 * i], y = xb[3 * i + 1], z = xb[3 * i + 2];
        unsigned cx = min(63u, (unsigned)(x * 64.0f));
        unsigned cy = min(63u, (unsigned)(y * 64.0f));
        unsigned cz = min(63u, (unsigned)(z * 64.0f));
        const unsigned m = (expand6(cz) << 2) | (expand6(cy) << 1) | expand6(cx);
        skey[i] = (m << 13) | (unsigned)i;
    }
    __syncthreads();

    // ---- phase B: bitonic sort (8192 u32) ----
    for (unsigned ksz = 2; ksz <= (unsigned)Nc; ksz <<= 1) {
        for (unsigned j = ksz >> 1; j > 0; j >>= 1) {
#pragma unroll 4
            for (int r = 0; r < 16; r++) {
                const int i = t + r * 512;
                const int p = i ^ (int)j;
                if (p > i) {
                    const unsigned a = skey[i], c = skey[p];
                    const bool up = ((i & (int)ksz) == 0);
                    if (up ? (a > c) : (a < c)) { skey[i] = c; skey[p] = a; }
                }
            }
            __syncthreads();
        }
    }

    // ---- phase C: gather owned points, bounding sphere ----
    ull pxp[8], pyp[8], pzp[8];
    unsigned oidxp[8];           // two u16 original indices per reg
    float cx_, cy_, cz_, rad;
    {
        float px[16], py[16], pz[16];
#pragma unroll
        for (int p = 0; p < 16; p++) {
            const unsigned oi = skey[16 * t + p] & 8191u;
            px[p] = xb[3 * oi];
            py[p] = xb[3 * oi + 1];
            pz[p] = xb[3 * oi + 2];
            if (p & 1) oidxp[p >> 1] |= oi << 16;
            else       oidxp[p >> 1]  = oi;
        }
#pragma unroll
        for (int i = 0; i < 8; i++) {
            pxp[i] = f2pack(px[2 * i], px[2 * i + 1]);
            pyp[i] = f2pack(py[2 * i], py[2 * i + 1]);
            pzp[i] = f2pack(pz[2 * i], pz[2 * i + 1]);
        }
        float mnx = px[0], mxx = px[0], mny = py[0], mxy = py[0], mnz = pz[0], mxz = pz[0];
#pragma unroll
        for (int p = 1; p < 16; p++) {
            mnx = fminf(mnx, px[p]); mxx = fmaxf(mxx, px[p]);
            mny = fminf(mny, py[p]); mxy = fmaxf(mxy, py[p]);
            mnz = fminf(mnz, pz[p]); mxz = fmaxf(mxz, pz[p]);
        }
        cx_ = 0.5f * (mnx + mxx); cy_ = 0.5f * (mny + mxy); cz_ = 0.5f * (mnz + mxz);
        float r2 = 0.0f;
#pragma unroll
        for (int p = 0; p < 16; p++) {
            const float dx = px[p] - cx_, dy = py[p] - cy_, dz = pz[p] - cz_;
            float d = dx * dx; d = fmaf(dy, dy, d); d = fmaf(dz, dz, d);
            r2 = fmaxf(r2, d);
        }
        rad = sqrtf(r2) * 1.001f + 1e-5f;   // inflated: covers fp error in bound
    }

    // ---- phase D: init distances to original point 0 ----
    float mind[16];
    float bv;
    int candc;                    // cached min original idx among {mind==bv}
    {
        const float qx = xb[0], qy = xb[1], qz = xb[2];
        const ull nqx = f2pack(-qx, -qx), nqy = f2pack(-qy, -qy), nqz = f2pack(-qz, -qz);
        float g[8];
#pragma unroll
        for (int i = 0; i < 8; i++) {
            ull dx = f2add(pxp[i], nqx);
            ull dy = f2add(pyp[i], nqy);
            ull dz = f2add(pzp[i], nqz);
            ull d = f2mul(dx, dx); d = f2fma(dy, dy, d); d = f2fma(dz, dz, d);
            const float2 dd = f2unpack(d);
            mind[2 * i]     = dd.x;
            mind[2 * i + 1] = dd.y;
            g[i] = fmaxf(dd.x, dd.y);
        }
        const float t0 = fmaxf(fmaxf(g[0], g[1]), fmaxf(g[2], g[3]));
        const float t1 = fmaxf(fmaxf(g[4], g[5]), fmaxf(g[6], g[7]));
        bv = fmaxf(t0, t1);
        const unsigned bvb = __float_as_uint(bv);
        candc = 0x7fffffff;
#pragma unroll
        for (int p = 0; p < 16; p++)
            if (__float_as_uint(mind[p]) == bvb) {
                const int oi = (int)((oidxp[p >> 1] >> ((p & 1) * 16)) & 0xffffu);
                candc = min(candc, oi);
            }
    }
    if (t == 0) g_fidx[b * NPc] = 0;
    __syncthreads();

    // cached squared prune threshold: ((rad + sqrt(bv)) * 1.0005)^2
    float sthr2;
    {
        const float s = (rad + sqrtf(bv)) * 1.0005f;
        sthr2 = s * s;
    }

    // ---- phase E: main loop ----
    for (int k = 1; k < NPc; k++) {
        const int s = k & 1;
        // stage 1: lane0 ST.64-resets the slot, then ALL lanes atomicMax their
        // packed key. u64 order == (value desc, original index asc). No REDUX.
        const unsigned bvb = __float_as_uint(bv);
        if (lane == 0) skeys[s][wid] = 0ull;
        atomicMax(&skeys[s][wid], ((ull)bvb << 32) | (unsigned)(8191 - candc));
        __syncthreads();

        // stage 2: one LDS.64 per lane (16 slots, lanes 16-31 duplicate),
        // then REDUX.MAX on value + REDUX.MIN on matching original index.
        const ull kk = skeys[s][lane & 15];
        const unsigned wv = (unsigned)(kk >> 32);
        const int      wi = 8191 - (int)((unsigned)kk & 0x1FFFu);
        const unsigned gbest = __reduce_max_sync(0xffffffffu, wv);
        const int gcand = (wv == gbest) ? wi : 0x7fffffff;
        const int w = __reduce_min_sync(0xffffffffu, gcand);
        if (t == 0) g_fidx[b * NPc + k] = w;

        // broadcast load of winner coords (L1-resident, same-address broadcast)
        const float qx = xb[w * 3], qy = xb[w * 3 + 1], qz = xb[w * 3 + 2];

        // exact prune via cached squared threshold
        const float ex = cx_ - qx, ey = cy_ - qy, ez = cz_ - qz;
        float dqc2 = ex * ex; dqc2 = fmaf(ey, ey, dqc2); dqc2 = fmaf(ez, ez, dqc2);
        if (dqc2 < sthr2) {
            const ull nqx = f2pack(-qx, -qx), nqy = f2pack(-qy, -qy), nqz = f2pack(-qz, -qz);
            float g[8];
#pragma unroll
            for (int i = 0; i < 8; i++) {
                ull dx = f2add(pxp[i], nqx);
                ull dy = f2add(pyp[i], nqy);
                ull dz = f2add(pzp[i], nqz);
                ull d = f2mul(dx, dx); d = f2fma(dy, dy, d); d = f2fma(dz, dz, d);
                const float2 dd = f2unpack(d);
                const float m0 = fminf(mind[2 * i],     dd.x);
                const float m1 = fminf(mind[2 * i + 1], dd.y);
                mind[2 * i]     = m0;
                mind[2 * i + 1] = m1;
                g[i] = fmaxf(m0, m1);
            }
            const float t0 = fmaxf(fmaxf(g[0], g[1]), fmaxf(g[2], g[3]));
            const float t1 = fmaxf(fmaxf(g[4], g[5]), fmaxf(g[6], g[7]));
            bv = fmaxf(t0, t1);
            // recompute caches (hidden under next iteration's latency)
            const unsigned nb = __float_as_uint(bv);
            int cc = 0x7fffffff;
#pragma unroll
            for (int p = 0; p < 16; p++)
                if (__float_as_uint(mind[p]) == nb) {
                    const int oi = (int)((oidxp[p >> 1] >> ((p & 1) * 16)) & 0xffffu);
                    cc = min(cc, oi);
                }
            candc = cc;
            const float sn = (rad + sqrtf(bv)) * 1.0005f;
            sthr2 = sn * sn;
        }
    }
}

// ---------------------------------------------------------------------------
// 2) Transpose feats [B, CIN, N] -> featsT [B, N, CIN] for coalesced gathers
// ---------------------------------------------------------------------------
__global__ void __launch_bounds__(256) transpose_kernel(const float* __restrict__ feats) {
    __shared__ float tile[32][33];
    const int b  = blockIdx.z;
    const int n0 = blockIdx.x * 32;
    const int c0 = blockIdx.y * 32;
    const int x = threadIdx.x, y = threadIdx.y;
#pragma unroll
    for (int r = 0; r < 32; r += 8)
        tile[y + r][x] = feats[(size_t)(b * CINc + c0 + y + r) * Nc + n0 + x];
    __syncthreads();
#pragma unroll
    for (int r = 0; r < 32; r += 8)
        g_featsT[(size_t)(b * Nc + n0 + y + r) * CINc + c0 + x] = tile[x][y + r];
}

// ---------------------------------------------------------------------------
// 3) Ball query (warp 0, ballot-compaction with early exit) + gather + maxpool
//    (128 channel-threads). One block per query point.
// ---------------------------------------------------------------------------
__global__ void __launch_bounds__(128) pool_kernel(const float* __restrict__ xyz) {
    const int b = blockIdx.x >> 11;     // / NPc
    const int j = blockIdx.x & (NPc - 1);
    __shared__ int sidx[NSc];
    const int tid = threadIdx.x;

    if (tid < 32) {
        const float* xb = xyz + (size_t)b * Nc * 3;
        const int fi = g_fidx[b * NPc + j];
        const float qx = xb[fi * 3], qy = xb[fi * 3 + 1], qz = xb[fi * 3 + 2];
        const float R2 = 0.04f;  // float(0.04): matches JAX weak-typed 0.2*0.2 promotion
        int count = 0;
        for (int base = 0; base < Nc && count < NSc; base += 32) {
            const int i = base + tid;
            float dx = xb[i * 3] - qx, dy = xb[i * 3 + 1] - qy, dz = xb[i * 3 + 2] - qz;
            float d = dx * dx; d = fmaf(dy, dy, d); d = fmaf(dz, dz, d);
            const bool in = d < R2;
            const unsigned m = __ballot_sync(0xffffffffu, in);
            const int pos = count + __popc(m & ((1u << tid) - 1u));
            if (in && pos < NSc) sidx[pos] = i;
            count += __popc(m);
        }
        __syncwarp();
        // pad with first neighbor (count >= 1 always: query pt is in its own ball)
        const int first = (count > 0) ? sidx[0] : 0;
        for (int s = count + tid; s < NSc; s += 32) sidx[s] = first;
    }
    __syncthreads();

    const float* ft = g_featsT + (size_t)b * Nc * CINc;
    const int c = tid;  // 128 threads == CIN channels
    float m = __int_as_float(0xff800000);  // -inf
#pragma unroll
    for (int s = 0; s < NSc; s++)
        m = fmaxf(m, ft[(size_t)sidx[s] * CINc + c]);
    g_pooledT[((size_t)(b * NPc + j)) * CINc + c] = m;
}

// ---------------------------------------------------------------------------
// 4) out[b,o,j] = lrelu( (W[o,:] . pooledT[b,j,:]) * inv[o] + (beta - rmean*inv)[o] )
//    64x64 shared-tiled SIMT GEMM, 4x4 per-thread microtile, float4 stores.
// ---------------------------------------------------------------------------
__global__ void __launch_bounds__(256) gemm_bn_relu_kernel(
    const float* __restrict__ W,
    const float* __restrict__ gamma, const float* __restrict__ beta,
    const float* __restrict__ rmean, const float* __restrict__ rvar,
    float* __restrict__ out)
{
    __shared__ float Ws[64][33];
    __shared__ float Ps[64][33];
    const int b  = blockIdx.z;
    const int j0 = blockIdx.x * 64;
    const int o0 = blockIdx.y * 64;
    const int tid = threadIdx.x;
    const int tx = tid & 15, ty = tid >> 4;

    const float* Pbase = g_pooledT + ((size_t)b * NPc + j0) * CINc;

    float acc[4][4];
#pragma unroll
    for (int i = 0; i < 4; i++)
#pragma unroll
        for (int jj = 0; jj < 4; jj++) acc[i][jj] = 0.0f;

    for (int k0 = 0; k0 < CINc; k0 += 32) {
#pragma unroll
        for (int l = 0; l < 8; l++) {
            const int idx = tid + l * 256;
            const int r = idx >> 5, kk = idx & 31;
            Ws[r][kk] = W[(size_t)(o0 + r) * CINc + k0 + kk];
            Ps[r][kk] = Pbase[(size_t)r * CINc + k0 + kk];
        }
        __syncthreads();
#pragma unroll
        for (int k = 0; k < 32; k++) {
            const float a0 = Ws[ty * 4 + 0][k], a1 = Ws[ty * 4 + 1][k];
            const float a2 = Ws[ty * 4 + 2][k], a3 = Ws[ty * 4 + 3][k];
            const float p0 = Ps[tx * 4 + 0][k], p1 = Ps[tx * 4 + 1][k];
            const float p2 = Ps[tx * 4 + 2][k], p3 = Ps[tx * 4 + 3][k];
            acc[0][0] += a0 * p0; acc[0][1] += a0 * p1; acc[0][2] += a0 * p2; acc[0][3] += a0 * p3;
            acc[1][0] += a1 * p0; acc[1][1] += a1 * p1; acc[1][2] += a1 * p2; acc[1][3] += a1 * p3;
            acc[2][0] += a2 * p0; acc[2][1] += a2 * p1; acc[2][2] += a2 * p2; acc[2][3] += a2 * p3;
            acc[3][0] += a3 * p0; acc[3][1] += a3 * p1; acc[3][2] += a3 * p2; acc[3][3] += a3 * p3;
        }
        __syncthreads();
    }

#pragma unroll
    for (int oi = 0; oi < 4; oi++) {
        const int o = o0 + ty * 4 + oi;
        const float inv  = gamma[o] / sqrtf(rvar[o] + 1e-5f);
        const float bias = fmaf(-rmean[o], inv, beta[o]);  // beta - rmean*inv
        float vs[4];
#pragma unroll
        for (int ji = 0; ji < 4; ji++) {
            const float y = fmaf(acc[oi][ji], inv, bias);
            vs[ji] = (y >= 0.0f) ? y : 0.2f * y;
        }
        float4 vv = make_float4(vs[0], vs[1], vs[2], vs[3]);
        *reinterpret_cast<float4*>(out + (size_t)(b * COUTc + o) * NPc + j0 + tx * 4) = vv;
    }
}

// ---------------------------------------------------------------------------
extern "C" void kernel_launch(void* const* d_in, const int* in_sizes, int n_in,
                              void* d_out, int out_size) {
    const float* xyz    = (const float*)d_in[0];
    const float* feats  = (const float*)d_in[1];
    const float* conv_w = (const float*)d_in[2];
    const float* gamma  = (const float*)d_in[3];
    const float* beta   = (const float*)d_in[4];
    const float* rmean  = (const float*)d_in[5];
    const float* rvar   = (const float*)d_in[6];
    float* out = (float*)d_out;

    transpose_kernel<<<dim3(Nc / 32, CINc / 32, Bc), dim3(32, 8)>>>(feats);
    fps_kernel<<<Bc, 512>>>(xyz);
    pool_kernel<<<Bc * NPc, 128>>>(xyz);
    gemm_bn_relu_kernel<<<dim3(NPc / 64, COUTc / 64, Bc), 256>>>(
        conv_w, gamma, beta, rmean, rvar, out);
}

// round 15
// speedup vs baseline: 1.5829x; 1.5829x over previous
#include <cuda_runtime.h>

#define Bc 4
#define Nc 8192
#define NPc 2048
#define NSc 32
#define CINc 128
#define COUTc 256

// Scratch (no cudaMalloc allowed): device globals
__device__ int   g_fidx[Bc * NPc];
__device__ float g_featsT[(size_t)Bc * Nc * CINc];    // [B, N, CIN]  16 MB
__device__ float g_pooledT[(size_t)Bc * NPc * CINc];  // [B, NP, CIN]  4 MB

// ---------------- packed f32x2 helpers (sm_103a) ----------------
// NOTE: only add/mul/fma exist in f32x2 form; min/max do NOT (ptxas rejects).
typedef unsigned long long ull;

__device__ __forceinline__ ull f2pack(float lo, float hi) {
    ull r; asm("mov.b64 %0, {%1, %2};" : "=l"(r) : "f"(lo), "f"(hi)); return r;
}
__device__ __forceinline__ float2 f2unpack(ull v) {
    float2 f; asm("mov.b64 {%0, %1}, %2;" : "=f"(f.x), "=f"(f.y) : "l"(v)); return f;
}
__device__ __forceinline__ ull f2add(ull a, ull b) {
    ull r; asm("add.rn.f32x2 %0, %1, %2;" : "=l"(r) : "l"(a), "l"(b)); return r;
}
__device__ __forceinline__ ull f2mul(ull a, ull b) {
    ull r; asm("mul.rn.f32x2 %0, %1, %2;" : "=l"(r) : "l"(a), "l"(b)); return r;
}
__device__ __forceinline__ ull f2fma(ull a, ull b, ull c) {
    ull r; asm("fma.rn.f32x2 %0, %1, %2, %3;" : "=l"(r) : "l"(a), "l"(b), "l"(c)); return r;
}

__device__ __forceinline__ unsigned expand6(unsigned v) {  // 6 bits -> every 3rd bit
    v = (v * 0x00010001u) & 0xFF0000FFu;
    v = (v * 0x00000101u) & 0x0F00F00Fu;
    v = (v * 0x00000011u) & 0xC30C30C3u;
    v = (v * 0x00000005u) & 0x49249249u;
    return v;
}

// ---------------------------------------------------------------------------
// 1) Furthest point sampling (R13 structure — best known: 512 threads/block,
//    16 Morton-contiguous points/thread, bitonic-sorted in shared, exact
//    per-thread bounding-sphere pruning; flat, branch-minimal).
//    Reduction per iteration (one __syncthreads):
//      stage 1: REDUX.MAX on value bits; lane 0 does ONE ST.64 initializing
//      this warp's u64 slot to (best<<32 | 0x7fffffff); then lanes with
//      bv==best atomicMin their cached candc into the slot's LOW word.
//      (Same-warp same-address shared ops complete in program order ->
//      write-before-use, no extra buffering. Predicated atomic: expected
//      issuers ~1 — NEVER use a full-warp same-address atomic here; that
//      serializes ~32x and regressed badly in R14.)
//      stage 2: ONE LDS.64 per lane (16 slots), REDUX.MAX on value +
//      REDUX.MIN on matching index.
//    Double-buffered by parity: reader of slot s at iter k finishes before
//    bar(k+1); next writer of slot s (iter k+2) starts after bar(k+1).
//    candc (thread-local min original idx among {mind[p]==bv}) and the squared
//    prune threshold are cached, recomputed only in the update branch.
//    Tie-break = lowest original index, exact.
// ---------------------------------------------------------------------------
__global__ void __launch_bounds__(512, 1) fps_kernel(const float* __restrict__ xyz) {
    const int b = blockIdx.x;
    const float* xb = xyz + (size_t)b * Nc * 3;
    const int t = threadIdx.x;
    const int lane = t & 31;
    const int wid = t >> 5;

    __shared__ unsigned skey[Nc];               // 32 KB: (morton18 << 13) | idx13
    __shared__ __align__(16) ull skeys[2][16];  // per-warp (value<<32 | minidx)

    // ---- phase A: build sort keys ----
#pragma unroll
    for (int r = 0; r < 16; r++) {
        const int i = t + r * 512;
        const float x = xb[3 * i], y = xb[3 * i + 1], z = xb[3 * i + 2];
        unsigned cx = min(63u, (unsigned)(x * 64.0f));
        unsigned cy = min(63u, (unsigned)(y * 64.0f));
        unsigned cz = min(63u, (unsigned)(z * 64.0f));
        const unsigned m = (expand6(cz) << 2) | (expand6(cy) << 1) | expand6(cx);
        skey[i] = (m << 13) | (unsigned)i;
    }
    __syncthreads();

    // ---- phase B: bitonic sort (8192 u32) ----
    for (unsigned ksz = 2; ksz <= (unsigned)Nc; ksz <<= 1) {
        for (unsigned j = ksz >> 1; j > 0; j >>= 1) {
#pragma unroll 4
            for (int r = 0; r < 16; r++) {
                const int i = t + r * 512;
                const int p = i ^ (int)j;
                if (p > i) {
                    const unsigned a = skey[i], c = skey[p];
                    const bool up = ((i & (int)ksz) == 0);
                    if (up ? (a > c) : (a < c)) { skey[i] = c; skey[p] = a; }
                }
            }
            __syncthreads();
        }
    }

    // ---- phase C: gather owned points, bounding sphere ----
    ull pxp[8], pyp[8], pzp[8];
    unsigned oidxp[8];           // two u16 original indices per reg
    float cx_, cy_, cz_, rad;
    {
        float px[16], py[16], pz[16];
#pragma unroll
        for (int p = 0; p < 16; p++) {
            const unsigned oi = skey[16 * t + p] & 8191u;
            px[p] = xb[3 * oi];
            py[p] = xb[3 * oi + 1];
            pz[p] = xb[3 * oi + 2];
            if (p & 1) oidxp[p >> 1] |= oi << 16;
            else       oidxp[p >> 1]  = oi;
        }
#pragma unroll
        for (int i = 0; i < 8; i++) {
            pxp[i] = f2pack(px[2 * i], px[2 * i + 1]);
            pyp[i] = f2pack(py[2 * i], py[2 * i + 1]);
            pzp[i] = f2pack(pz[2 * i], pz[2 * i + 1]);
        }
        float mnx = px[0], mxx = px[0], mny = py[0], mxy = py[0], mnz = pz[0], mxz = pz[0];
#pragma unroll
        for (int p = 1; p < 16; p++) {
            mnx = fminf(mnx, px[p]); mxx = fmaxf(mxx, px[p]);
            mny = fminf(mny, py[p]); mxy = fmaxf(mxy, py[p]);
            mnz = fminf(mnz, pz[p]); mxz = fmaxf(mxz, pz[p]);
        }
        cx_ = 0.5f * (mnx + mxx); cy_ = 0.5f * (mny + mxy); cz_ = 0.5f * (mnz + mxz);
        float r2 = 0.0f;
#pragma unroll
        for (int p = 0; p < 16; p++) {
            const float dx = px[p] - cx_, dy = py[p] - cy_, dz = pz[p] - cz_;
            float d = dx * dx; d = fmaf(dy, dy, d); d = fmaf(dz, dz, d);
            r2 = fmaxf(r2, d);
        }
        rad = sqrtf(r2) * 1.001f + 1e-5f;   // inflated: covers fp error in bound
    }

    // ---- phase D: init distances to original point 0 ----
    float mind[16];
    float bv;
    int candc;                    // cached min original idx among {mind==bv}
    {
        const float qx = xb[0], qy = xb[1], qz = xb[2];
        const ull nqx = f2pack(-qx, -qx), nqy = f2pack(-qy, -qy), nqz = f2pack(-qz, -qz);
        float g[8];
#pragma unroll
        for (int i = 0; i < 8; i++) {
            ull dx = f2add(pxp[i], nqx);
            ull dy = f2add(pyp[i], nqy);
            ull dz = f2add(pzp[i], nqz);
            ull d = f2mul(dx, dx); d = f2fma(dy, dy, d); d = f2fma(dz, dz, d);
            const float2 dd = f2unpack(d);
            mind[2 * i]     = dd.x;
            mind[2 * i + 1] = dd.y;
            g[i] = fmaxf(dd.x, dd.y);
        }
        const float t0 = fmaxf(fmaxf(g[0], g[1]), fmaxf(g[2], g[3]));
        const float t1 = fmaxf(fmaxf(g[4], g[5]), fmaxf(g[6], g[7]));
        bv = fmaxf(t0, t1);
        const unsigned bvb = __float_as_uint(bv);
        candc = 0x7fffffff;
#pragma unroll
        for (int p = 0; p < 16; p++)
            if (__float_as_uint(mind[p]) == bvb) {
                const int oi = (int)((oidxp[p >> 1] >> ((p & 1) * 16)) & 0xffffu);
                candc = min(candc, oi);
            }
    }
    if (t == 0) g_fidx[b * NPc] = 0;
    __syncthreads();

    // cached squared prune threshold: ((rad + sqrt(bv)) * 1.0005)^2
    float sthr2;
    {
        const float s = (rad + sqrtf(bv)) * 1.0005f;
        sthr2 = s * s;
    }

    // ---- phase E: main loop ----
    for (int k = 1; k < NPc; k++) {
        const int s = k & 1;
        // stage 1: REDUX.MAX; lane0 ST.64-inits this warp's slot, then
        // matching lanes (expected ~1) atomicMin the low word.
        const unsigned bvb = __float_as_uint(bv);
        const unsigned best = __reduce_max_sync(0xffffffffu, bvb);
        if (lane == 0) skeys[s][wid] = ((ull)best << 32) | 0x7fffffffull;
        if (bvb == best) atomicMin((int*)&skeys[s][wid], candc);   // low word
        __syncthreads();

        // stage 2: one LDS.64 per lane (16 slots, lanes 16-31 duplicate),
        // then REDUX.MAX on value + REDUX.MIN on matching index.
        const ull kk = skeys[s][lane & 15];
        const unsigned wv = (unsigned)(kk >> 32);
        const int      wi = (int)(unsigned)kk;
        const unsigned gbest = __reduce_max_sync(0xffffffffu, wv);
        const int gcand = (wv == gbest) ? wi : 0x7fffffff;
        const int w = __reduce_min_sync(0xffffffffu, gcand);
        if (t == 0) g_fidx[b * NPc + k] = w;

        // broadcast load of winner coords (L1-resident, same-address broadcast)
        const float qx = xb[w * 3], qy = xb[w * 3 + 1], qz = xb[w * 3 + 2];

        // exact prune via cached squared threshold
        const float ex = cx_ - qx, ey = cy_ - qy, ez = cz_ - qz;
        float dqc2 = ex * ex; dqc2 = fmaf(ey, ey, dqc2); dqc2 = fmaf(ez, ez, dqc2);
        if (dqc2 < sthr2) {
            const ull nqx = f2pack(-qx, -qx), nqy = f2pack(-qy, -qy), nqz = f2pack(-qz, -qz);
            float g[8];
#pragma unroll
            for (int i = 0; i < 8; i++) {
                ull dx = f2add(pxp[i], nqx);
                ull dy = f2add(pyp[i], nqy);
                ull dz = f2add(pzp[i], nqz);
                ull d = f2mul(dx, dx); d = f2fma(dy, dy, d); d = f2fma(dz, dz, d);
                const float2 dd = f2unpack(d);
                const float m0 = fminf(mind[2 * i],     dd.x);
                const float m1 = fminf(mind[2 * i + 1], dd.y);
                mind[2 * i]     = m0;
                mind[2 * i + 1] = m1;
                g[i] = fmaxf(m0, m1);
            }
            const float t0 = fmaxf(fmaxf(g[0], g[1]), fmaxf(g[2], g[3]));
            const float t1 = fmaxf(fmaxf(g[4], g[5]), fmaxf(g[6], g[7]));
            bv = fmaxf(t0, t1);
            // recompute caches (hidden under next iteration's REDUX latency)
            const unsigned nb = __float_as_uint(bv);
            int cc = 0x7fffffff;
#pragma unroll
            for (int p = 0; p < 16; p++)
                if (__float_as_uint(mind[p]) == nb) {
                    const int oi = (int)((oidxp[p >> 1] >> ((p & 1) * 16)) & 0xffffu);
                    cc = min(cc, oi);
                }
            candc = cc;
            const float sn = (rad + sqrtf(bv)) * 1.0005f;
            sthr2 = sn * sn;
        }
    }
}

// ---------------------------------------------------------------------------
// 2) Transpose feats [B, CIN, N] -> featsT [B, N, CIN] for coalesced gathers
// ---------------------------------------------------------------------------
__global__ void __launch_bounds__(256) transpose_kernel(const float* __restrict__ feats) {
    __shared__ float tile[32][33];
    const int b  = blockIdx.z;
    const int n0 = blockIdx.x * 32;
    const int c0 = blockIdx.y * 32;
    const int x = threadIdx.x, y = threadIdx.y;
#pragma unroll
    for (int r = 0; r < 32; r += 8)
        tile[y + r][x] = feats[(size_t)(b * CINc + c0 + y + r) * Nc + n0 + x];
    __syncthreads();
#pragma unroll
    for (int r = 0; r < 32; r += 8)
        g_featsT[(size_t)(b * Nc + n0 + y + r) * CINc + c0 + x] = tile[x][y + r];
}

// ---------------------------------------------------------------------------
// 3) Ball query (warp 0, ballot-compaction with early exit) + gather + maxpool
//    (128 channel-threads). One block per query point.
// ---------------------------------------------------------------------------
__global__ void __launch_bounds__(128) pool_kernel(const float* __restrict__ xyz) {
    const int b = blockIdx.x >> 11;     // / NPc
    const int j = blockIdx.x & (NPc - 1);
    __shared__ int sidx[NSc];
    const int tid = threadIdx.x;

    if (tid < 32) {
        const float* xb = xyz + (size_t)b * Nc * 3;
        const int fi = g_fidx[b * NPc + j];
        const float qx = xb[fi * 3], qy = xb[fi * 3 + 1], qz = xb[fi * 3 + 2];
        const float R2 = 0.04f;  // float(0.04): matches JAX weak-typed 0.2*0.2 promotion
        int count = 0;
        for (int base = 0; base < Nc && count < NSc; base += 32) {
            const int i = base + tid;
            float dx = xb[i * 3] - qx, dy = xb[i * 3 + 1] - qy, dz = xb[i * 3 + 2] - qz;
            float d = dx * dx; d = fmaf(dy, dy, d); d = fmaf(dz, dz, d);
            const bool in = d < R2;
            const unsigned m = __ballot_sync(0xffffffffu, in);
            const int pos = count + __popc(m & ((1u << tid) - 1u));
            if (in && pos < NSc) sidx[pos] = i;
            count += __popc(m);
        }
        __syncwarp();
        // pad with first neighbor (count >= 1 always: query pt is in its own ball)
        const int first = (count > 0) ? sidx[0] : 0;
        for (int s = count + tid; s < NSc; s += 32) sidx[s] = first;
    }
    __syncthreads();

    const float* ft = g_featsT + (size_t)b * Nc * CINc;
    const int c = tid;  // 128 threads == CIN channels
    float m = __int_as_float(0xff800000);  // -inf
#pragma unroll
    for (int s = 0; s < NSc; s++)
        m = fmaxf(m, ft[(size_t)sidx[s] * CINc + c]);
    g_pooledT[((size_t)(b * NPc + j)) * CINc + c] = m;
}

// ---------------------------------------------------------------------------
// 4) out[b,o,j] = lrelu( (W[o,:] . pooledT[b,j,:]) * inv[o] + (beta - rmean*inv)[o] )
//    64x64 shared-tiled SIMT GEMM, 4x4 per-thread microtile, float4 stores.
// ---------------------------------------------------------------------------
__global__ void __launch_bounds__(256) gemm_bn_relu_kernel(
    const float* __restrict__ W,
    const float* __restrict__ gamma, const float* __restrict__ beta,
    const float* __restrict__ rmean, const float* __restrict__ rvar,
    float* __restrict__ out)
{
    __shared__ float Ws[64][33];
    __shared__ float Ps[64][33];
    const int b  = blockIdx.z;
    const int j0 = blockIdx.x * 64;
    const int o0 = blockIdx.y * 64;
    const int tid = threadIdx.x;
    const int tx = tid & 15, ty = tid >> 4;

    const float* Pbase = g_pooledT + ((size_t)b * NPc + j0) * CINc;

    float acc[4][4];
#pragma unroll
    for (int i = 0; i < 4; i++)
#pragma unroll
        for (int jj = 0; jj < 4; jj++) acc[i][jj] = 0.0f;

    for (int k0 = 0; k0 < CINc; k0 += 32) {
#pragma unroll
        for (int l = 0; l < 8; l++) {
            const int idx = tid + l * 256;
            const int r = idx >> 5, kk = idx & 31;
            Ws[r][kk] = W[(size_t)(o0 + r) * CINc + k0 + kk];
            Ps[r][kk] = Pbase[(size_t)r * CINc + k0 + kk];
        }
        __syncthreads();
#pragma unroll
        for (int k = 0; k < 32; k++) {
            const float a0 = Ws[ty * 4 + 0][k], a1 = Ws[ty * 4 + 1][k];
            const float a2 = Ws[ty * 4 + 2][k], a3 = Ws[ty * 4 + 3][k];
            const float p0 = Ps[tx * 4 + 0][k], p1 = Ps[tx * 4 + 1][k];
            const float p2 = Ps[tx * 4 + 2][k], p3 = Ps[tx * 4 + 3][k];
            acc[0][0] += a0 * p0; acc[0][1] += a0 * p1; acc[0][2] += a0 * p2; acc[0][3] += a0 * p3;
            acc[1][0] += a1 * p0; acc[1][1] += a1 * p1; acc[1][2] += a1 * p2; acc[1][3] += a1 * p3;
            acc[2][0] += a2 * p0; acc[2][1] += a2 * p1; acc[2][2] += a2 * p2; acc[2][3] += a2 * p3;
            acc[3][0] += a3 * p0; acc[3][1] += a3 * p1; acc[3][2] += a3 * p2; acc[3][3] += a3 * p3;
        }
        __syncthreads();
    }

#pragma unroll
    for (int oi = 0; oi < 4; oi++) {
        const int o = o0 + ty * 4 + oi;
        const float inv  = gamma[o] / sqrtf(rvar[o] + 1e-5f);
        const float bias = fmaf(-rmean[o], inv, beta[o]);  // beta - rmean*inv
        float vs[4];
#pragma unroll
        for (int ji = 0; ji < 4; ji++) {
            const float y = fmaf(acc[oi][ji], inv, bias);
            vs[ji] = (y >= 0.0f) ? y : 0.2f * y;
        }
        float4 vv = make_float4(vs[0], vs[1], vs[2], vs[3]);
        *reinterpret_cast<float4*>(out + (size_t)(b * COUTc + o) * NPc + j0 + tx * 4) = vv;
    }
}

// ---------------------------------------------------------------------------
extern "C" void kernel_launch(void* const* d_in, const int* in_sizes, int n_in,
                              void* d_out, int out_size) {
    const float* xyz    = (const float*)d_in[0];
    const float* feats  = (const float*)d_in[1];
    const float* conv_w = (const float*)d_in[2];
    const float* gamma  = (const float*)d_in[3];
    const float* beta   = (const float*)d_in[4];
    const float* rmean  = (const float*)d_in[5];
    const float* rvar   = (const float*)d_in[6];
    float* out = (float*)d_out;

    transpose_kernel<<<dim3(Nc / 32, CINc / 32, Bc), dim3(32, 8)>>>(feats);
    fps_kernel<<<Bc, 512>>>(xyz);
    pool_kernel<<<Bc * NPc, 128>>>(xyz);
    gemm_bn_relu_kernel<<<dim3(NPc / 64, COUTc / 64, Bc), 256>>>(
        conv_w, gamma, beta, rmean, rvar, out);
}

// round 16
// speedup vs baseline: 1.6038x; 1.0132x over previous
#include <cuda_runtime.h>

#define Bc 4
#define Nc 8192
#define NPc 2048
#define NSc 32
#define CINc 128
#define COUTc 256

// Scratch (no cudaMalloc allowed): device globals
__device__ int   g_fidx[Bc * NPc];
__device__ float g_featsT[(size_t)Bc * Nc * CINc];    // [B, N, CIN]  16 MB
__device__ float g_pooledT[(size_t)Bc * NPc * CINc];  // [B, NP, CIN]  4 MB

// ---------------- packed f32x2 helpers (sm_103a) ----------------
// NOTE: only add/mul/fma exist in f32x2 form; min/max do NOT (ptxas rejects).
typedef unsigned long long ull;

__device__ __forceinline__ ull f2pack(float lo, float hi) {
    ull r; asm("mov.b64 %0, {%1, %2};" : "=l"(r) : "f"(lo), "f"(hi)); return r;
}
__device__ __forceinline__ float2 f2unpack(ull v) {
    float2 f; asm("mov.b64 {%0, %1}, %2;" : "=f"(f.x), "=f"(f.y) : "l"(v)); return f;
}
__device__ __forceinline__ ull f2add(ull a, ull b) {
    ull r; asm("add.rn.f32x2 %0, %1, %2;" : "=l"(r) : "l"(a), "l"(b)); return r;
}
__device__ __forceinline__ ull f2mul(ull a, ull b) {
    ull r; asm("mul.rn.f32x2 %0, %1, %2;" : "=l"(r) : "l"(a), "l"(b)); return r;
}
__device__ __forceinline__ ull f2fma(ull a, ull b, ull c) {
    ull r; asm("fma.rn.f32x2 %0, %1, %2, %3;" : "=l"(r) : "l"(a), "l"(b), "l"(c)); return r;
}

__device__ __forceinline__ unsigned expand6(unsigned v) {  // 6 bits -> every 3rd bit
    v = (v * 0x00010001u) & 0xFF0000FFu;
    v = (v * 0x00000101u) & 0x0F00F00Fu;
    v = (v * 0x00000011u) & 0xC30C30C3u;
    v = (v * 0x00000005u) & 0x49249249u;
    return v;
}

// Dynamic shared layout for fps_kernel:
//   [0, 32768)        unsigned skey[8192]    (morton18<<13 | idx13)
//   [32768, 163840)   float4  sxyz4[8192]    xyz shadow, ORIGINAL index
//   [163840, 164096)  ull     skeys[2][16]   per-warp (value<<32 | minidx)
#define FPS_SMEM_BYTES 164096
#define SKEY_OFF  0
#define SXYZ_OFF  32768
#define SKEYS_OFF 163840

// ---------------------------------------------------------------------------
// 1) Furthest point sampling (R13 structure — best known: 512 threads/block,
//    16 Morton-contiguous points/thread, bitonic-sorted in shared, exact
//    per-thread bounding-sphere pruning; flat, branch-minimal).
//    R16 delta: xyz kept as a float4 shadow in SHARED (filled in phase A) so
//    the per-iteration winner-coordinate fetch is ONE broadcast LDS.128
//    (29 cyc, 1 issue) instead of 3x LDG.32 (39 cyc, 3 issues). Coordinates
//    are bit-identical copies -> selections unchanged.
//    Reduction per iteration (one __syncthreads):
//      stage 1: REDUX.MAX on value bits; lane 0 ST.64-inits this warp's u64
//      slot to (best<<32 | 0x7fffffff); lanes with bv==best (expected ~1)
//      atomicMin cached candc into the LOW word. (Same-warp same-address
//      shared ops are program-ordered -> write-before-use. NEVER a full-warp
//      same-address atomic: that serializes ~32x — R14 regression.)
//      stage 2: ONE LDS.64 per lane (16 slots), REDUX.MAX value +
//      REDUX.MIN matching index.
//    Double-buffered by parity. candc + squared prune threshold cached,
//    recomputed only in the update branch. Tie-break = lowest original index.
// ---------------------------------------------------------------------------
__global__ void __launch_bounds__(512, 1) fps_kernel(const float* __restrict__ xyz) {
    extern __shared__ __align__(16) char smem_raw[];
    unsigned* skey  = reinterpret_cast<unsigned*>(smem_raw + SKEY_OFF);
    float4*   sxyz4 = reinterpret_cast<float4*>(smem_raw + SXYZ_OFF);
    ull*      skeys = reinterpret_cast<ull*>(smem_raw + SKEYS_OFF); // [2][16]

    const int b = blockIdx.x;
    const float* xb = xyz + (size_t)b * Nc * 3;
    const int t = threadIdx.x;
    const int lane = t & 31;
    const int wid = t >> 5;

    // ---- phase A: build sort keys + fill shared float4 xyz shadow ----
#pragma unroll
    for (int r = 0; r < 16; r++) {
        const int i = t + r * 512;
        const float x = xb[3 * i], y = xb[3 * i + 1], z = xb[3 * i + 2];
        sxyz4[i] = make_float4(x, y, z, 0.0f);
        unsigned cx = min(63u, (unsigned)(x * 64.0f));
        unsigned cy = min(63u, (unsigned)(y * 64.0f));
        unsigned cz = min(63u, (unsigned)(z * 64.0f));
        const unsigned m = (expand6(cz) << 2) | (expand6(cy) << 1) | expand6(cx);
        skey[i] = (m << 13) | (unsigned)i;
    }
    __syncthreads();

    // ---- phase B: bitonic sort (8192 u32) ----
    for (unsigned ksz = 2; ksz <= (unsigned)Nc; ksz <<= 1) {
        for (unsigned j = ksz >> 1; j > 0; j >>= 1) {
#pragma unroll 4
            for (int r = 0; r < 16; r++) {
                const int i = t + r * 512;
                const int p = i ^ (int)j;
                if (p > i) {
                    const unsigned a = skey[i], c = skey[p];
                    const bool up = ((i & (int)ksz) == 0);
                    if (up ? (a > c) : (a < c)) { skey[i] = c; skey[p] = a; }
                }
            }
            __syncthreads();
        }
    }

    // ---- phase C: gather owned points (from shared shadow), bounding sphere
    ull pxp[8], pyp[8], pzp[8];
    unsigned oidxp[8];           // two u16 original indices per reg
    float cx_, cy_, cz_, rad;
    {
        float px[16], py[16], pz[16];
#pragma unroll
        for (int p = 0; p < 16; p++) {
            const unsigned oi = skey[16 * t + p] & 8191u;
            const float4 c4 = sxyz4[oi];
            px[p] = c4.x; py[p] = c4.y; pz[p] = c4.z;
            if (p & 1) oidxp[p >> 1] |= oi << 16;
            else       oidxp[p >> 1]  = oi;
        }
#pragma unroll
        for (int i = 0; i < 8; i++) {
            pxp[i] = f2pack(px[2 * i], px[2 * i + 1]);
            pyp[i] = f2pack(py[2 * i], py[2 * i + 1]);
            pzp[i] = f2pack(pz[2 * i], pz[2 * i + 1]);
        }
        float mnx = px[0], mxx = px[0], mny = py[0], mxy = py[0], mnz = pz[0], mxz = pz[0];
#pragma unroll
        for (int p = 1; p < 16; p++) {
            mnx = fminf(mnx, px[p]); mxx = fmaxf(mxx, px[p]);
            mny = fminf(mny, py[p]); mxy = fmaxf(mxy, py[p]);
            mnz = fminf(mnz, pz[p]); mxz = fmaxf(mxz, pz[p]);
        }
        cx_ = 0.5f * (mnx + mxx); cy_ = 0.5f * (mny + mxy); cz_ = 0.5f * (mnz + mxz);
        float r2 = 0.0f;
#pragma unroll
        for (int p = 0; p < 16; p++) {
            const float dx = px[p] - cx_, dy = py[p] - cy_, dz = pz[p] - cz_;
            float d = dx * dx; d = fmaf(dy, dy, d); d = fmaf(dz, dz, d);
            r2 = fmaxf(r2, d);
        }
        rad = sqrtf(r2) * 1.001f + 1e-5f;   // inflated: covers fp error in bound
    }

    // ---- phase D: init distances to original point 0 ----
    float mind[16];
    float bv;
    int candc;                    // cached min original idx among {mind==bv}
    {
        const float4 q0 = sxyz4[0];
        const ull nqx = f2pack(-q0.x, -q0.x), nqy = f2pack(-q0.y, -q0.y), nqz = f2pack(-q0.z, -q0.z);
        float g[8];
#pragma unroll
        for (int i = 0; i < 8; i++) {
            ull dx = f2add(pxp[i], nqx);
            ull dy = f2add(pyp[i], nqy);
            ull dz = f2add(pzp[i], nqz);
            ull d = f2mul(dx, dx); d = f2fma(dy, dy, d); d = f2fma(dz, dz, d);
            const float2 dd = f2unpack(d);
            mind[2 * i]     = dd.x;
            mind[2 * i + 1] = dd.y;
            g[i] = fmaxf(dd.x, dd.y);
        }
        const float t0 = fmaxf(fmaxf(g[0], g[1]), fmaxf(g[2], g[3]));
        const float t1 = fmaxf(fmaxf(g[4], g[5]), fmaxf(g[6], g[7]));
        bv = fmaxf(t0, t1);
        const unsigned bvb = __float_as_uint(bv);
        candc = 0x7fffffff;
#pragma unroll
        for (int p = 0; p < 16; p++)
            if (__float_as_uint(mind[p]) == bvb) {
                const int oi = (int)((oidxp[p >> 1] >> ((p & 1) * 16)) & 0xffffu);
                candc = min(candc, oi);
            }
    }
    if (t == 0) g_fidx[b * NPc] = 0;
    __syncthreads();

    // cached squared prune threshold: ((rad + sqrt(bv)) * 1.0005)^2
    float sthr2;
    {
        const float s = (rad + sqrtf(bv)) * 1.0005f;
        sthr2 = s * s;
    }

    // ---- phase E: main loop ----
    for (int k = 1; k < NPc; k++) {
        const int s = k & 1;
        // stage 1: REDUX.MAX; lane0 ST.64-inits this warp's slot, then
        // matching lanes (expected ~1) atomicMin the low word.
        const unsigned bvb = __float_as_uint(bv);
        const unsigned best = __reduce_max_sync(0xffffffffu, bvb);
        if (lane == 0) skeys[s * 16 + wid] = ((ull)best << 32) | 0x7fffffffull;
        if (bvb == best) atomicMin((int*)&skeys[s * 16 + wid], candc);   // low word
        __syncthreads();

        // stage 2: one LDS.64 per lane (16 slots, lanes 16-31 duplicate),
        // then REDUX.MAX on value + REDUX.MIN on matching index.
        const ull kk = skeys[s * 16 + (lane & 15)];
        const unsigned wv = (unsigned)(kk >> 32);
        const int      wi = (int)(unsigned)kk;
        const unsigned gbest = __reduce_max_sync(0xffffffffu, wv);
        const int gcand = (wv == gbest) ? wi : 0x7fffffff;
        const int w = __reduce_min_sync(0xffffffffu, gcand);
        if (t == 0) g_fidx[b * NPc + k] = w;

        // winner coords: ONE broadcast LDS.128 from the shared shadow
        const float4 q4 = sxyz4[w];

        // exact prune via cached squared threshold
        const float ex = cx_ - q4.x, ey = cy_ - q4.y, ez = cz_ - q4.z;
        float dqc2 = ex * ex; dqc2 = fmaf(ey, ey, dqc2); dqc2 = fmaf(ez, ez, dqc2);
        if (dqc2 < sthr2) {
            const ull nqx = f2pack(-q4.x, -q4.x), nqy = f2pack(-q4.y, -q4.y), nqz = f2pack(-q4.z, -q4.z);
            float g[8];
#pragma unroll
            for (int i = 0; i < 8; i++) {
                ull dx = f2add(pxp[i], nqx);
                ull dy = f2add(pyp[i], nqy);
                ull dz = f2add(pzp[i], nqz);
                ull d = f2mul(dx, dx); d = f2fma(dy, dy, d); d = f2fma(dz, dz, d);
                const float2 dd = f2unpack(d);
                const float m0 = fminf(mind[2 * i],     dd.x);
                const float m1 = fminf(mind[2 * i + 1], dd.y);
                mind[2 * i]     = m0;
                mind[2 * i + 1] = m1;
                g[i] = fmaxf(m0, m1);
            }
            const float t0 = fmaxf(fmaxf(g[0], g[1]), fmaxf(g[2], g[3]));
            const float t1 = fmaxf(fmaxf(g[4], g[5]), fmaxf(g[6], g[7]));
            bv = fmaxf(t0, t1);
            // recompute caches (hidden under next iteration's REDUX latency)
            const unsigned nb = __float_as_uint(bv);
            int cc = 0x7fffffff;
#pragma unroll
            for (int p = 0; p < 16; p++)
                if (__float_as_uint(mind[p]) == nb) {
                    const int oi = (int)((oidxp[p >> 1] >> ((p & 1) * 16)) & 0xffffu);
                    cc = min(cc, oi);
                }
            candc = cc;
            const float sn = (rad + sqrtf(bv)) * 1.0005f;
            sthr2 = sn * sn;
        }
    }
}

// ---------------------------------------------------------------------------
// 2) Transpose feats [B, CIN, N] -> featsT [B, N, CIN] for coalesced gathers
// ---------------------------------------------------------------------------
__global__ void __launch_bounds__(256) transpose_kernel(const float* __restrict__ feats) {
    __shared__ float tile[32][33];
    const int b  = blockIdx.z;
    const int n0 = blockIdx.x * 32;
    const int c0 = blockIdx.y * 32;
    const int x = threadIdx.x, y = threadIdx.y;
#pragma unroll
    for (int r = 0; r < 32; r += 8)
        tile[y + r][x] = feats[(size_t)(b * CINc + c0 + y + r) * Nc + n0 + x];
    __syncthreads();
#pragma unroll
    for (int r = 0; r < 32; r += 8)
        g_featsT[(size_t)(b * Nc + n0 + y + r) * CINc + c0 + x] = tile[x][y + r];
}

// ---------------------------------------------------------------------------
// 3) Ball query (warp 0, ballot-compaction with early exit) + gather + maxpool
//    (128 channel-threads). One block per query point.
// ---------------------------------------------------------------------------
__global__ void __launch_bounds__(128) pool_kernel(const float* __restrict__ xyz) {
    const int b = blockIdx.x >> 11;     // / NPc
    const int j = blockIdx.x & (NPc - 1);
    __shared__ int sidx[NSc];
    const int tid = threadIdx.x;

    if (tid < 32) {
        const float* xb = xyz + (size_t)b * Nc * 3;
        const int fi = g_fidx[b * NPc + j];
        const float qx = xb[fi * 3], qy = xb[fi * 3 + 1], qz = xb[fi * 3 + 2];
        const float R2 = 0.04f;  // float(0.04): matches JAX weak-typed 0.2*0.2 promotion
        int count = 0;
        for (int base = 0; base < Nc && count < NSc; base += 32) {
            const int i = base + tid;
            float dx = xb[i * 3] - qx, dy = xb[i * 3 + 1] - qy, dz = xb[i * 3 + 2] - qz;
            float d = dx * dx; d = fmaf(dy, dy, d); d = fmaf(dz, dz, d);
            const bool in = d < R2;
            const unsigned m = __ballot_sync(0xffffffffu, in);
            const int pos = count + __popc(m & ((1u << tid) - 1u));
            if (in && pos < NSc) sidx[pos] = i;
            count += __popc(m);
        }
        __syncwarp();
        // pad with first neighbor (count >= 1 always: query pt is in its own ball)
        const int first = (count > 0) ? sidx[0] : 0;
        for (int s = count + tid; s < NSc; s += 32) sidx[s] = first;
    }
    __syncthreads();

    const float* ft = g_featsT + (size_t)b * Nc * CINc;
    const int c = tid;  // 128 threads == CIN channels
    float m = __int_as_float(0xff800000);  // -inf
#pragma unroll
    for (int s = 0; s < NSc; s++)
        m = fmaxf(m, ft[(size_t)sidx[s] * CINc + c]);
    g_pooledT[((size_t)(b * NPc + j)) * CINc + c] = m;
}

// ---------------------------------------------------------------------------
// 4) out[b,o,j] = lrelu( (W[o,:] . pooledT[b,j,:]) * inv[o] + (beta - rmean*inv)[o] )
//    64x64 shared-tiled SIMT GEMM, 4x4 per-thread microtile, float4 stores.
// ---------------------------------------------------------------------------
__global__ void __launch_bounds__(256) gemm_bn_relu_kernel(
    const float* __restrict__ W,
    const float* __restrict__ gamma, const float* __restrict__ beta,
    const float* __restrict__ rmean, const float* __restrict__ rvar,
    float* __restrict__ out)
{
    __shared__ float Ws[64][33];
    __shared__ float Ps[64][33];
    const int b  = blockIdx.z;
    const int j0 = blockIdx.x * 64;
    const int o0 = blockIdx.y * 64;
    const int tid = threadIdx.x;
    const int tx = tid & 15, ty = tid >> 4;

    const float* Pbase = g_pooledT + ((size_t)b * NPc + j0) * CINc;

    float acc[4][4];
#pragma unroll
    for (int i = 0; i < 4; i++)
#pragma unroll
        for (int jj = 0; jj < 4; jj++) acc[i][jj] = 0.0f;

    for (int k0 = 0; k0 < CINc; k0 += 32) {
#pragma unroll
        for (int l = 0; l < 8; l++) {
            const int idx = tid + l * 256;
            const int r = idx >> 5, kk = idx & 31;
            Ws[r][kk] = W[(size_t)(o0 + r) * CINc + k0 + kk];
            Ps[r][kk] = Pbase[(size_t)r * CINc + k0 + kk];
        }
        __syncthreads();
#pragma unroll
        for (int k = 0; k < 32; k++) {
            const float a0 = Ws[ty * 4 + 0][k], a1 = Ws[ty * 4 + 1][k];
            const float a2 = Ws[ty * 4 + 2][k], a3 = Ws[ty * 4 + 3][k];
            const float p0 = Ps[tx * 4 + 0][k], p1 = Ps[tx * 4 + 1][k];
            const float p2 = Ps[tx * 4 + 2][k], p3 = Ps[tx * 4 + 3][k];
            acc[0][0] += a0 * p0; acc[0][1] += a0 * p1; acc[0][2] += a0 * p2; acc[0][3] += a0 * p3;
            acc[1][0] += a1 * p0; acc[1][1] += a1 * p1; acc[1][2] += a1 * p2; acc[1][3] += a1 * p3;
            acc[2][0] += a2 * p0; acc[2][1] += a2 * p1; acc[2][2] += a2 * p2; acc[2][3] += a2 * p3;
            acc[3][0] += a3 * p0; acc[3][1] += a3 * p1; acc[3][2] += a3 * p2; acc[3][3] += a3 * p3;
        }
        __syncthreads();
    }

#pragma unroll
    for (int oi = 0; oi < 4; oi++) {
        const int o = o0 + ty * 4 + oi;
        const float inv  = gamma[o] / sqrtf(rvar[o] + 1e-5f);
        const float bias = fmaf(-rmean[o], inv, beta[o]);  // beta - rmean*inv
        float vs[4];
#pragma unroll
        for (int ji = 0; ji < 4; ji++) {
            const float y = fmaf(acc[oi][ji], inv, bias);
            vs[ji] = (y >= 0.0f) ? y : 0.2f * y;
        }
        float4 vv = make_float4(vs[0], vs[1], vs[2], vs[3]);
        *reinterpret_cast<float4*>(out + (size_t)(b * COUTc + o) * NPc + j0 + tx * 4) = vv;
    }
}

// ---------------------------------------------------------------------------
extern "C" void kernel_launch(void* const* d_in, const int* in_sizes, int n_in,
                              void* d_out, int out_size) {
    const float* xyz    = (const float*)d_in[0];
    const float* feats  = (const float*)d_in[1];
    const float* conv_w = (const float*)d_in[2];
    const float* gamma  = (const float*)d_in[3];
    const float* beta   = (const float*)d_in[4];
    const float* rmean  = (const float*)d_in[5];
    const float* rvar   = (const float*)d_in[6];
    float* out = (float*)d_out;

    // Opt-in to >48KB dynamic shared for fps_kernel (idempotent; not a stream
    // op -> graph-capture safe; no allocation).
    cudaFuncSetAttribute(fps_kernel, cudaFuncAttributeMaxDynamicSharedMemorySize,
                         FPS_SMEM_BYTES);

    transpose_kernel<<<dim3(Nc / 32, CINc / 32, Bc), dim3(32, 8)>>>(feats);
    fps_kernel<<<Bc, 512, FPS_SMEM_BYTES>>>(xyz);
    pool_kernel<<<Bc * NPc, 128>>>(xyz);
    gemm_bn_relu_kernel<<<dim3(NPc / 64, COUTc / 64, Bc), 256>>>(
        conv_w, gamma, beta, rmean, rvar, out);
}

// round 17
// speedup vs baseline: 1.6061x; 1.0015x over previous
#include <cuda_runtime.h>

#define Bc 4
#define Nc 8192
#define NPc 2048
#define NSc 32
#define CINc 128
#define COUTc 256

// Scratch (no cudaMalloc allowed): device globals
__device__ int   g_fidx[Bc * NPc];
__device__ float g_featsT[(size_t)Bc * Nc * CINc];    // [B, N, CIN]  16 MB
__device__ float g_pooledT[(size_t)Bc * NPc * CINc];  // [B, NP, CIN]  4 MB

// ---------------- packed f32x2 helpers (sm_103a) ----------------
// NOTE: only add/mul/fma exist in f32x2 form; min/max do NOT (ptxas rejects).
typedef unsigned long long ull;

__device__ __forceinline__ ull f2pack(float lo, float hi) {
    ull r; asm("mov.b64 %0, {%1, %2};" : "=l"(r) : "f"(lo), "f"(hi)); return r;
}
__device__ __forceinline__ float2 f2unpack(ull v) {
    float2 f; asm("mov.b64 {%0, %1}, %2;" : "=f"(f.x), "=f"(f.y) : "l"(v)); return f;
}
__device__ __forceinline__ ull f2add(ull a, ull b) {
    ull r; asm("add.rn.f32x2 %0, %1, %2;" : "=l"(r) : "l"(a), "l"(b)); return r;
}
__device__ __forceinline__ ull f2mul(ull a, ull b) {
    ull r; asm("mul.rn.f32x2 %0, %1, %2;" : "=l"(r) : "l"(a), "l"(b)); return r;
}
__device__ __forceinline__ ull f2fma(ull a, ull b, ull c) {
    ull r; asm("fma.rn.f32x2 %0, %1, %2, %3;" : "=l"(r) : "l"(a), "l"(b), "l"(c)); return r;
}

__device__ __forceinline__ unsigned expand6(unsigned v) {  // 6 bits -> every 3rd bit
    v = (v * 0x00010001u) & 0xFF0000FFu;
    v = (v * 0x00000101u) & 0x0F00F00Fu;
    v = (v * 0x00000011u) & 0xC30C30C3u;
    v = (v * 0x00000005u) & 0x49249249u;
    return v;
}

// Dynamic shared layout for the mega kernel (FPS blocks):
//   [0, 32768)        unsigned skey[8192]    (morton18<<13 | idx13)
//   [32768, 163840)   float4  sxyz4[8192]    xyz shadow, ORIGINAL index
//   [163840, 164096)  ull     skeys[2][16]   per-warp (value<<32 | minidx)
// Transpose blocks reuse the first 4224 bytes as a float tile[32][33].
#define FPS_SMEM_BYTES 164096
#define SKEY_OFF  0
#define SXYZ_OFF  32768
#define SKEYS_OFF 163840

// ---------------------------------------------------------------------------
// FPS body (blocks 0..3). R16 structure (best known) + R17 split slot-init:
//   stage 1: lane 0 resets the slot's LOW word (index floor) BEFORE the
//   REDUX (overlapped), stores the HIGH word (best) after; lanes with
//   bv==best (expected ~1) atomicMin cached candc into the low word.
//   Same-warp same-address shared ops are program-ordered (R13-proven).
//   stage 2: ONE LDS.64 per lane (16 slots), REDUX.MAX value + REDUX.MIN idx.
//   Winner coords: ONE broadcast LDS.128 from the shared xyz shadow.
//   Double-buffered by parity; candc + squared prune threshold cached,
//   recomputed only in the update branch. Tie-break = lowest original index.
// ---------------------------------------------------------------------------
__device__ void fps_body(const float* __restrict__ xyz, char* smem_raw) {
    unsigned* skey  = reinterpret_cast<unsigned*>(smem_raw + SKEY_OFF);
    float4*   sxyz4 = reinterpret_cast<float4*>(smem_raw + SXYZ_OFF);
    ull*      skeys = reinterpret_cast<ull*>(smem_raw + SKEYS_OFF); // [2][16]

    const int b = blockIdx.x;
    const float* xb = xyz + (size_t)b * Nc * 3;
    const int t = threadIdx.x;
    const int lane = t & 31;
    const int wid = t >> 5;

    // ---- phase A: build sort keys + fill shared float4 xyz shadow ----
#pragma unroll
    for (int r = 0; r < 16; r++) {
        const int i = t + r * 512;
        const float x = xb[3 * i], y = xb[3 * i + 1], z = xb[3 * i + 2];
        sxyz4[i] = make_float4(x, y, z, 0.0f);
        unsigned cx = min(63u, (unsigned)(x * 64.0f));
        unsigned cy = min(63u, (unsigned)(y * 64.0f));
        unsigned cz = min(63u, (unsigned)(z * 64.0f));
        const unsigned m = (expand6(cz) << 2) | (expand6(cy) << 1) | expand6(cx);
        skey[i] = (m << 13) | (unsigned)i;
    }
    __syncthreads();

    // ---- phase B: bitonic sort (8192 u32) ----
    for (unsigned ksz = 2; ksz <= (unsigned)Nc; ksz <<= 1) {
        for (unsigned j = ksz >> 1; j > 0; j >>= 1) {
#pragma unroll 4
            for (int r = 0; r < 16; r++) {
                const int i = t + r * 512;
                const int p = i ^ (int)j;
                if (p > i) {
                    const unsigned a = skey[i], c = skey[p];
                    const bool up = ((i & (int)ksz) == 0);
                    if (up ? (a > c) : (a < c)) { skey[i] = c; skey[p] = a; }
                }
            }
            __syncthreads();
        }
    }

    // ---- phase C: gather owned points (from shared shadow), bounding sphere
    ull pxp[8], pyp[8], pzp[8];
    unsigned oidxp[8];           // two u16 original indices per reg
    float cx_, cy_, cz_, rad;
    {
        float px[16], py[16], pz[16];
#pragma unroll
        for (int p = 0; p < 16; p++) {
            const unsigned oi = skey[16 * t + p] & 8191u;
            const float4 c4 = sxyz4[oi];
            px[p] = c4.x; py[p] = c4.y; pz[p] = c4.z;
            if (p & 1) oidxp[p >> 1] |= oi << 16;
            else       oidxp[p >> 1]  = oi;
        }
#pragma unroll
        for (int i = 0; i < 8; i++) {
            pxp[i] = f2pack(px[2 * i], px[2 * i + 1]);
            pyp[i] = f2pack(py[2 * i], py[2 * i + 1]);
            pzp[i] = f2pack(pz[2 * i], pz[2 * i + 1]);
        }
        float mnx = px[0], mxx = px[0], mny = py[0], mxy = py[0], mnz = pz[0], mxz = pz[0];
#pragma unroll
        for (int p = 1; p < 16; p++) {
            mnx = fminf(mnx, px[p]); mxx = fmaxf(mxx, px[p]);
            mny = fminf(mny, py[p]); mxy = fmaxf(mxy, py[p]);
            mnz = fminf(mnz, pz[p]); mxz = fmaxf(mxz, pz[p]);
        }
        cx_ = 0.5f * (mnx + mxx); cy_ = 0.5f * (mny + mxy); cz_ = 0.5f * (mnz + mxz);
        float r2 = 0.0f;
#pragma unroll
        for (int p = 0; p < 16; p++) {
            const float dx = px[p] - cx_, dy = py[p] - cy_, dz = pz[p] - cz_;
            float d = dx * dx; d = fmaf(dy, dy, d); d = fmaf(dz, dz, d);
            r2 = fmaxf(r2, d);
        }
        rad = sqrtf(r2) * 1.001f + 1e-5f;   // inflated: covers fp error in bound
    }

    // ---- phase D: init distances to original point 0 ----
    float mind[16];
    float bv;
    int candc;                    // cached min original idx among {mind==bv}
    {
        const float4 q0 = sxyz4[0];
        const ull nqx = f2pack(-q0.x, -q0.x), nqy = f2pack(-q0.y, -q0.y), nqz = f2pack(-q0.z, -q0.z);
        float g[8];
#pragma unroll
        for (int i = 0; i < 8; i++) {
            ull dx = f2add(pxp[i], nqx);
            ull dy = f2add(pyp[i], nqy);
            ull dz = f2add(pzp[i], nqz);
            ull d = f2mul(dx, dx); d = f2fma(dy, dy, d); d = f2fma(dz, dz, d);
            const float2 dd = f2unpack(d);
            mind[2 * i]     = dd.x;
            mind[2 * i + 1] = dd.y;
            g[i] = fmaxf(dd.x, dd.y);
        }
        const float t0 = fmaxf(fmaxf(g[0], g[1]), fmaxf(g[2], g[3]));
        const float t1 = fmaxf(fmaxf(g[4], g[5]), fmaxf(g[6], g[7]));
        bv = fmaxf(t0, t1);
        const unsigned bvb = __float_as_uint(bv);
        candc = 0x7fffffff;
#pragma unroll
        for (int p = 0; p < 16; p++)
            if (__float_as_uint(mind[p]) == bvb) {
                const int oi = (int)((oidxp[p >> 1] >> ((p & 1) * 16)) & 0xffffu);
                candc = min(candc, oi);
            }
    }
    if (t == 0) g_fidx[b * NPc] = 0;
    __syncthreads();

    // cached squared prune threshold: ((rad + sqrt(bv)) * 1.0005)^2
    float sthr2;
    {
        const float s = (rad + sqrtf(bv)) * 1.0005f;
        sthr2 = s * s;
    }

    // ---- phase E: main loop ----
    for (int k = 1; k < NPc; k++) {
        const int s = k & 1;
        unsigned* slot32 = reinterpret_cast<unsigned*>(&skeys[s * 16 + wid]);
        // stage 1: low-word reset BEFORE the REDUX (overlapped); high word
        // (best) after; matching lanes (expected ~1) atomicMin the low word.
        const unsigned bvb = __float_as_uint(bv);
        if (lane == 0) slot32[0] = 0x7fffffffu;          // index floor (low)
        const unsigned best = __reduce_max_sync(0xffffffffu, bvb);
        if (lane == 0) slot32[1] = best;                 // value (high)
        if (bvb == best) atomicMin((int*)slot32, candc); // low word
        __syncthreads();

        // stage 2: one LDS.64 per lane (16 slots, lanes 16-31 duplicate),
        // then REDUX.MAX on value + REDUX.MIN on matching index.
        const ull kk = skeys[s * 16 + (lane & 15)];
        const unsigned wv = (unsigned)(kk >> 32);
        const int      wi = (int)(unsigned)kk;
        const unsigned gbest = __reduce_max_sync(0xffffffffu, wv);
        const int gcand = (wv == gbest) ? wi : 0x7fffffff;
        const int w = __reduce_min_sync(0xffffffffu, gcand);
        if (t == 0) g_fidx[b * NPc + k] = w;

        // winner coords: ONE broadcast LDS.128 from the shared shadow
        const float4 q4 = sxyz4[w];

        // exact prune via cached squared threshold
        const float ex = cx_ - q4.x, ey = cy_ - q4.y, ez = cz_ - q4.z;
        float dqc2 = ex * ex; dqc2 = fmaf(ey, ey, dqc2); dqc2 = fmaf(ez, ez, dqc2);
        if (dqc2 < sthr2) {
            const ull nqx = f2pack(-q4.x, -q4.x), nqy = f2pack(-q4.y, -q4.y), nqz = f2pack(-q4.z, -q4.z);
            float g[8];
#pragma unroll
            for (int i = 0; i < 8; i++) {
                ull dx = f2add(pxp[i], nqx);
                ull dy = f2add(pyp[i], nqy);
                ull dz = f2add(pzp[i], nqz);
                ull d = f2mul(dx, dx); d = f2fma(dy, dy, d); d = f2fma(dz, dz, d);
                const float2 dd = f2unpack(d);
                const float m0 = fminf(mind[2 * i],     dd.x);
                const float m1 = fminf(mind[2 * i + 1], dd.y);
                mind[2 * i]     = m0;
                mind[2 * i + 1] = m1;
                g[i] = fmaxf(m0, m1);
            }
            const float t0 = fmaxf(fmaxf(g[0], g[1]), fmaxf(g[2], g[3]));
            const float t1 = fmaxf(fmaxf(g[4], g[5]), fmaxf(g[6], g[7]));
            bv = fmaxf(t0, t1);
            // recompute caches (hidden under next iteration's REDUX latency)
            const unsigned nb = __float_as_uint(bv);
            int cc = 0x7fffffff;
#pragma unroll
            for (int p = 0; p < 16; p++)
                if (__float_as_uint(mind[p]) == nb) {
                    const int oi = (int)((oidxp[p >> 1] >> ((p & 1) * 16)) & 0xffffu);
                    cc = min(cc, oi);
                }
            candc = cc;
            const float sn = (rad + sqrtf(bv)) * 1.0005f;
            sthr2 = sn * sn;
        }
    }
}

// ---------------------------------------------------------------------------
// Transpose body (blocks 4..4099): one 32x32 tile of
// feats [B, CIN, N] -> g_featsT [B, N, CIN]. 512 threads = (x:32, y:16),
// two row-halves r in {0,16}. Independent of FPS: runs on idle SMs
// concurrently, removing the standalone transpose launch from the timeline.
// ---------------------------------------------------------------------------
__device__ void transpose_body(const float* __restrict__ feats, char* smem_raw) {
    float (*tile)[33] = reinterpret_cast<float(*)[33]>(smem_raw);
    const int tb = blockIdx.x - Bc;          // 0..4095
    const int b     = tb >> 10;              // 1024 tiles per batch
    const int rem   = tb & 1023;
    const int c0    = (rem >> 8) * 32;       // 4 c-tiles
    const int n0    = (rem & 255) * 32;      // 256 n-tiles
    const int x = threadIdx.x & 31;
    const int y = threadIdx.x >> 5;          // 0..15
#pragma unroll
    for (int r = 0; r < 32; r += 16)
        tile[y + r][x] = feats[(size_t)(b * CINc + c0 + y + r) * Nc + n0 + x];
    __syncthreads();
#pragma unroll
    for (int r = 0; r < 32; r += 16)
        g_featsT[(size_t)(b * Nc + n0 + y + r) * CINc + c0 + x] = tile[x][y + r];
}

__global__ void __launch_bounds__(512, 1) fps_transpose_kernel(
    const float* __restrict__ xyz, const float* __restrict__ feats)
{
    extern __shared__ __align__(16) char smem_raw[];
    if (blockIdx.x < Bc) fps_body(xyz, smem_raw);
    else                 transpose_body(feats, smem_raw);
}

// ---------------------------------------------------------------------------
// 3) Ball query (warp 0, ballot-compaction with early exit) + gather + maxpool
//    (128 channel-threads). One block per query point.
// ---------------------------------------------------------------------------
__global__ void __launch_bounds__(128) pool_kernel(const float* __restrict__ xyz) {
    const int b = blockIdx.x >> 11;     // / NPc
    const int j = blockIdx.x & (NPc - 1);
    __shared__ int sidx[NSc];
    const int tid = threadIdx.x;

    if (tid < 32) {
        const float* xb = xyz + (size_t)b * Nc * 3;
        const int fi = g_fidx[b * NPc + j];
        const float qx = xb[fi * 3], qy = xb[fi * 3 + 1], qz = xb[fi * 3 + 2];
        const float R2 = 0.04f;  // float(0.04): matches JAX weak-typed 0.2*0.2 promotion
        int count = 0;
        for (int base = 0; base < Nc && count < NSc; base += 32) {
            const int i = base + tid;
            float dx = xb[i * 3] - qx, dy = xb[i * 3 + 1] - qy, dz = xb[i * 3 + 2] - qz;
            float d = dx * dx; d = fmaf(dy, dy, d); d = fmaf(dz, dz, d);
            const bool in = d < R2;
            const unsigned m = __ballot_sync(0xffffffffu, in);
            const int pos = count + __popc(m & ((1u << tid) - 1u));
            if (in && pos < NSc) sidx[pos] = i;
            count += __popc(m);
        }
        __syncwarp();
        // pad with first neighbor (count >= 1 always: query pt is in its own ball)
        const int first = (count > 0) ? sidx[0] : 0;
        for (int s = count + tid; s < NSc; s += 32) sidx[s] = first;
    }
    __syncthreads();

    const float* ft = g_featsT + (size_t)b * Nc * CINc;
    const int c = tid;  // 128 threads == CIN channels
    float m = __int_as_float(0xff800000);  // -inf
#pragma unroll
    for (int s = 0; s < NSc; s++)
        m = fmaxf(m, ft[(size_t)sidx[s] * CINc + c]);
    g_pooledT[((size_t)(b * NPc + j)) * CINc + c] = m;
}

// ---------------------------------------------------------------------------
// 4) out[b,o,j] = lrelu( (W[o,:] . pooledT[b,j,:]) * inv[o] + (beta - rmean*inv)[o] )
//    64x64 shared-tiled SIMT GEMM, 4x4 per-thread microtile, float4 stores.
// ---------------------------------------------------------------------------
__global__ void __launch_bounds__(256) gemm_bn_relu_kernel(
    const float* __restrict__ W,
    const float* __restrict__ gamma, const float* __restrict__ beta,
    const float* __restrict__ rmean, const float* __restrict__ rvar,
    float* __restrict__ out)
{
    __shared__ float Ws[64][33];
    __shared__ float Ps[64][33];
    const int b  = blockIdx.z;
    const int j0 = blockIdx.x * 64;
    const int o0 = blockIdx.y * 64;
    const int tid = threadIdx.x;
    const int tx = tid & 15, ty = tid >> 4;

    const float* Pbase = g_pooledT + ((size_t)b * NPc + j0) * CINc;

    float acc[4][4];
#pragma unroll
    for (int i = 0; i < 4; i++)
#pragma unroll
        for (int jj = 0; jj < 4; jj++) acc[i][jj] = 0.0f;

    for (int k0 = 0; k0 < CINc; k0 += 32) {
#pragma unroll
        for (int l = 0; l < 8; l++) {
            const int idx = tid + l * 256;
            const int r = idx >> 5, kk = idx & 31;
            Ws[r][kk] = W[(size_t)(o0 + r) * CINc + k0 + kk];
            Ps[r][kk] = Pbase[(size_t)r * CINc + k0 + kk];
        }
        __syncthreads();
#pragma unroll
        for (int k = 0; k < 32; k++) {
            const float a0 = Ws[ty * 4 + 0][k], a1 = Ws[ty * 4 + 1][k];
            const float a2 = Ws[ty * 4 + 2][k], a3 = Ws[ty * 4 + 3][k];
            const float p0 = Ps[tx * 4 + 0][k], p1 = Ps[tx * 4 + 1][k];
            const float p2 = Ps[tx * 4 + 2][k], p3 = Ps[tx * 4 + 3][k];
            acc[0][0] += a0 * p0; acc[0][1] += a0 * p1; acc[0][2] += a0 * p2; acc[0][3] += a0 * p3;
            acc[1][0] += a1 * p0; acc[1][1] += a1 * p1; acc[1][2] += a1 * p2; acc[1][3] += a1 * p3;
            acc[2][0] += a2 * p0; acc[2][1] += a2 * p1; acc[2][2] += a2 * p2; acc[2][3] += a2 * p3;
            acc[3][0] += a3 * p0; acc[3][1] += a3 * p1; acc[3][2] += a3 * p2; acc[3][3] += a3 * p3;
        }
        __syncthreads();
    }

#pragma unroll
    for (int oi = 0; oi < 4; oi++) {
        const int o = o0 + ty * 4 + oi;
        const float inv  = gamma[o] / sqrtf(rvar[o] + 1e-5f);
        const float bias = fmaf(-rmean[o], inv, beta[o]);  // beta - rmean*inv
        float vs[4];
#pragma unroll
        for (int ji = 0; ji < 4; ji++) {
            const float y = fmaf(acc[oi][ji], inv, bias);
            vs[ji] = (y >= 0.0f) ? y : 0.2f * y;
        }
        float4 vv = make_float4(vs[0], vs[1], vs[2], vs[3]);
        *reinterpret_cast<float4*>(out + (size_t)(b * COUTc + o) * NPc + j0 + tx * 4) = vv;
    }
}

// ---------------------------------------------------------------------------
extern "C" void kernel_launch(void* const* d_in, const int* in_sizes, int n_in,
                              void* d_out, int out_size) {
    const float* xyz    = (const float*)d_in[0];
    const float* feats  = (const float*)d_in[1];
    const float* conv_w = (const float*)d_in[2];
    const float* gamma  = (const float*)d_in[3];
    const float* beta   = (const float*)d_in[4];
    const float* rmean  = (const float*)d_in[5];
    const float* rvar   = (const float*)d_in[6];
    float* out = (float*)d_out;

    // Opt-in to >48KB dynamic shared (idempotent; graph-capture safe; no alloc).
    cudaFuncSetAttribute(fps_transpose_kernel,
                         cudaFuncAttributeMaxDynamicSharedMemorySize, FPS_SMEM_BYTES);

    // Blocks 0..3: FPS (one per batch). Blocks 4..4099: transpose tiles,
    // retiring on idle SMs concurrently with FPS.
    fps_transpose_kernel<<<Bc + Bc * (Nc / 32) * (CINc / 32), 512, FPS_SMEM_BYTES>>>(xyz, feats);
    pool_kernel<<<Bc * NPc, 128>>>(xyz);
    gemm_bn_relu_kernel<<<dim3(NPc / 64, COUTc / 64, Bc), 256>>>(
        conv_w, gamma, beta, rmean, rvar, out);
}